// round 12
// baseline (speedup 1.0000x reference)
#include <cuda_runtime.h>
#include <cuda_bf16.h>
#include <cstdint>
#include <math.h>

// ---------------- problem constants ----------------
#define NN 8192
#define INF_ 128
#define OUTF 64

// grid decomposition for k_main
#define M_CTA 128        // rows per CTA
#define NSPLIT 7         // K splits (grid 64*7 = 448 CTAs ~= 148 SMs * 3)
#define NPART 7
#define KCHUNK 64        // cols per chunk
#define TOTCHUNK (NN / KCHUNK)   // 128

// ---------------- device scratch (no allocs allowed) ----------------
__device__ float4 g_rowf[NN];                       // (f1, e^f1, e^{0.2 f1}, 0)
__device__ float4 g_colf[NN];                       // (f2, e^{f2}, e^{0.2 f2}, 0)
__device__ uint32_t g_Bf[NN * OUTF];                // 2 MB  Ht tf32, permuted B-frag order
__device__ float g_num[NPART][NN * OUTF];           // 14 MB partial numerators
__device__ float g_den[NPART][NN];                  // partial denominators

// ---------------- smem layout for k_main (B + col factors only; adj goes LDG) ----------------
#define OFF_BF0  0                         // 16384 each: [s][f][lane][2] tf32
#define OFF_BF1  16384
#define OFF_CF0  32768                     // 1024 each: 64 x float4 col factors
#define OFF_CF1  33792
#define SMEM_BYTES 34816

// ---------------- helpers ----------------
__device__ __forceinline__ uint32_t smem_u32(const void* p) {
    uint32_t a;
    asm("{ .reg .u64 t; cvta.to.shared.u64 t, %1; cvt.u32.u64 %0, t; }" : "=r"(a) : "l"(p));
    return a;
}
#define CP16(dst, src) \
    asm volatile("cp.async.cg.shared.global [%0], [%1], 16;" :: "r"(dst), "l"(src) : "memory")
#define CP_COMMIT() asm volatile("cp.async.commit_group;" ::: "memory")
#define CP_WAIT1()  asm volatile("cp.async.wait_group 1;" ::: "memory")

__device__ __forceinline__ uint32_t f2tf32(float x) {
    uint32_t r;
    asm("cvt.rna.tf32.f32 %0, %1;" : "=r"(r) : "f"(x));
    return r;
}
__device__ __forceinline__ void mma_tf32(float& d0, float& d1, float& d2, float& d3,
                                         uint32_t a0, uint32_t a1, uint32_t a2, uint32_t a3,
                                         uint32_t b0, uint32_t b1) {
    asm volatile("mma.sync.aligned.m16n8k8.row.col.f32.tf32.tf32.f32 "
                 "{%0,%1,%2,%3}, {%4,%5,%6,%7}, {%8,%9}, {%0,%1,%2,%3};"
                 : "+f"(d0), "+f"(d1), "+f"(d2), "+f"(d3)
                 : "r"(a0), "r"(a1), "r"(a2), "r"(a3), "r"(b0), "r"(b1));
}

// ---------------- fused pre-pass: h = X@W, per-node factors, B fragments ----------------
// grid 256 x 32 rows, 256 threads: 16 threads per row-pair (rows r, r+16), 4 cols each.
// Column permutation for B (must match k_main): within chunk, local col
// jl -> (c = jl>>4, s = (jl>>1)&7, u = jl&1); k-pos p = c + 4u.
__global__ void __launch_bounds__(256) k_pre(const float* __restrict__ X,
                                             const float* __restrict__ W,
                                             const float* __restrict__ a) {
    extern __shared__ float dsm[];
    float* Ws = dsm;                    // [128*64]  32 KB
    float* Xs = dsm + INF_ * OUTF;      // [32*128]  16 KB
    float* as = Xs + 32 * INF_;         // [128]     512 B

    int tid = threadIdx.x;
    const float4* W4 = (const float4*)W;
    float4* Ws4 = (float4*)Ws;
#pragma unroll
    for (int q = 0; q < 8; q++) Ws4[tid + q * 256] = W4[tid + q * 256];
    int r0 = blockIdx.x * 32;
    const float4* X4 = (const float4*)(X + (size_t)r0 * INF_);
    float4* Xs4 = (float4*)Xs;
#pragma unroll
    for (int q = 0; q < 4; q++) Xs4[tid + q * 256] = X4[tid + q * 256];
    if (tid < 128) as[tid] = a[tid];
    __syncthreads();

    int r = tid >> 4;                 // 0..15 -> rows r and r+16
    int cg = (tid & 15) * 4;          // cols cg..cg+3
    int wcol = cg >> 2;               // 0..15 float4 column of W
    float acc0[4], acc1[4];
#pragma unroll
    for (int j = 0; j < 4; j++) { acc0[j] = 0.f; acc1[j] = 0.f; }

    const float4* Xs4v = (const float4*)Xs;
    const float4* Ws4v = (const float4*)Ws;
#pragma unroll 4
    for (int k4 = 0; k4 < 32; k4++) {
        float4 x0 = Xs4v[r * 32 + k4];
        float4 x1 = Xs4v[(r + 16) * 32 + k4];
        float4 w;
        w = Ws4v[(k4 * 4 + 0) * 16 + wcol];
        acc0[0] += x0.x * w.x; acc0[1] += x0.x * w.y; acc0[2] += x0.x * w.z; acc0[3] += x0.x * w.w;
        acc1[0] += x1.x * w.x; acc1[1] += x1.x * w.y; acc1[2] += x1.x * w.z; acc1[3] += x1.x * w.w;
        w = Ws4v[(k4 * 4 + 1) * 16 + wcol];
        acc0[0] += x0.y * w.x; acc0[1] += x0.y * w.y; acc0[2] += x0.y * w.z; acc0[3] += x0.y * w.w;
        acc1[0] += x1.y * w.x; acc1[1] += x1.y * w.y; acc1[2] += x1.y * w.z; acc1[3] += x1.y * w.w;
        w = Ws4v[(k4 * 4 + 2) * 16 + wcol];
        acc0[0] += x0.z * w.x; acc0[1] += x0.z * w.y; acc0[2] += x0.z * w.z; acc0[3] += x0.z * w.w;
        acc1[0] += x1.z * w.x; acc1[1] += x1.z * w.y; acc1[2] += x1.z * w.z; acc1[3] += x1.z * w.w;
        w = Ws4v[(k4 * 4 + 3) * 16 + wcol];
        acc0[0] += x0.w * w.x; acc0[1] += x0.w * w.y; acc0[2] += x0.w * w.z; acc0[3] += x0.w * w.w;
        acc1[0] += x1.w * w.x; acc1[1] += x1.w * w.y; acc1[2] += x1.w * w.z; acc1[3] += x1.w * w.w;
    }

    // f1/f2 for both rows, reduced over the 16 threads of each row
    float f1a = 0.f, f2a = 0.f, f1b = 0.f, f2b = 0.f;
#pragma unroll
    for (int j = 0; j < 4; j++) {
        f1a += acc0[j] * as[cg + j];  f2a += acc0[j] * as[64 + cg + j];
        f1b += acc1[j] * as[cg + j];  f2b += acc1[j] * as[64 + cg + j];
    }
#pragma unroll
    for (int o = 8; o > 0; o >>= 1) {
        f1a += __shfl_xor_sync(0xFFFFFFFF, f1a, o);
        f2a += __shfl_xor_sync(0xFFFFFFFF, f2a, o);
        f1b += __shfl_xor_sync(0xFFFFFFFF, f1b, o);
        f2b += __shfl_xor_sync(0xFFFFFFFF, f2b, o);
    }
    int rowA = r0 + r, rowB = r0 + r + 16;
    if ((tid & 15) == 0) {
        g_rowf[rowA] = make_float4(f1a, expf(f1a), expf(0.2f * f1a), 0.f);
        g_colf[rowA] = make_float4(f2a, expf(f2a), expf(0.2f * f2a), 0.f);
        g_rowf[rowB] = make_float4(f1b, expf(f1b), expf(0.2f * f1b), 0.f);
        g_colf[rowB] = make_float4(f2b, expf(f2b), expf(0.2f * f2b), 0.f);
    }

    // scatter B fragments with permuted col mapping
#pragma unroll
    for (int pass = 0; pass < 2; pass++) {
        int row = pass ? rowB : rowA;
        const float* av = pass ? acc1 : acc0;
        int chunk = row >> 6;
        int jl = row & 63;
        int cc = jl >> 4;
        int ss = (jl >> 1) & 7;
        int uu = jl & 1;
#pragma unroll
        for (int j = 0; j < 4; j++) {
            int n = cg + j;
            int f = n >> 3;
            int l = ((n & 7) << 2) | cc;
            g_Bf[(size_t)chunk * 4096 + (((ss * 8 + f) * 32 + l) << 1) + uu] = f2tf32(av[j]);
        }
    }
}

// ---------------- main kernel ----------------
// grid 448 x 128 threads: rb = blockIdx % 64 (row block of 128), split = blockIdx / 64.
// 4 warps x 32 rows. adj: direct LDG.128 (zero reuse -> no smem staging).
// Thread (c) owns cols [16c, 16c+16) of each chunk via the column permutation.
__global__ void __launch_bounds__(128, 3) k_main(const int* __restrict__ adj) {
    extern __shared__ char sm[];
    uint32_t sb = smem_u32(sm);

    int tid = threadIdx.x;
    int wid = tid >> 5;     // 0..3
    int lane = tid & 31;
    int g = lane >> 2;
    int c = lane & 3;

    int rb = blockIdx.x & 63;
    int split = blockIdx.x >> 6;     // 0..6
    int row0 = rb * M_CTA;
    int ck0 = (split * TOTCHUNK) / NSPLIT;
    int ck1 = ((split + 1) * TOTCHUNK) / NSPLIT;

    // row factors for this thread's 4 rows (g + 8q within warp's 32)
    float f1r[4], e1r[4], e1br[4];
    const int* aptr[4];
#pragma unroll
    for (int q = 0; q < 4; q++) {
        int row = row0 + wid * 32 + g + q * 8;
        float4 rf = g_rowf[row];
        f1r[q] = rf.x; e1r[q] = rf.y; e1br[q] = rf.z;
        aptr[q] = adj + (size_t)row * NN + 16 * c;
    }

    float acc[2][8][4];
#pragma unroll
    for (int i = 0; i < 2; i++)
#pragma unroll
        for (int f = 0; f < 8; f++)
#pragma unroll
            for (int q = 0; q < 4; q++) acc[i][f][q] = 0.f;

    float den[4] = {0.f, 0.f, 0.f, 0.f};

    const uint32_t bfOff[2] = {OFF_BF0, OFF_BF1};
    const uint32_t cfOff[2] = {OFF_CF0, OFF_CF1};

    auto prefetch = [&](int ck, int buf) {
        // B fragments: 16 KB contiguous at g_Bf byte offset ck*16384
        const char* bsrc = (const char*)g_Bf + (size_t)ck * 16384;
        uint32_t bdst = sb + bfOff[buf];
#pragma unroll
        for (int p = 0; p < 8; p++) {
            int piece = tid + p * 128;
            CP16(bdst + piece * 16, bsrc + piece * 16);
        }
        // col factors: 64 x float4
        if (tid < 64) {
            CP16(sb + cfOff[buf] + tid * 16, (const char*)(g_colf + ck * KCHUNK + tid));
        }
    };

    prefetch(ck0, 0); CP_COMMIT();
    prefetch(ck0 + 1, 1); CP_COMMIT();

    for (int ck = ck0; ck < ck1; ++ck) {
        int buf = (ck - ck0) & 1;
        CP_WAIT1();
        __syncthreads();

        const uint32_t* bS = (const uint32_t*)(sm + bfOff[buf]);
        const float4* cfS = (const float4*)(sm + cfOff[buf]);
        int K0 = ck * KCHUNK;

        // adj register pipeline: int4 m covers cols 16c+4m.. (s-pair m = s>>1)
        int4 adjb[2][4];
#pragma unroll
        for (int q = 0; q < 4; q++)
            adjb[0][q] = __ldg((const int4*)(aptr[q] + K0));

#pragma unroll
        for (int s = 0; s < 8; s++) {
            int m = s >> 1;
            if ((s & 1) == 0 && m < 3) {
#pragma unroll
                for (int q = 0; q < 4; q++)
                    adjb[(m + 1) & 1][q] = __ldg((const int4*)(aptr[q] + K0 + 4 * (m + 1)));
            }
            int col0 = 16 * c + 2 * s;          // local col for u=0
            float4 c0 = cfS[col0];
            float4 c1 = cfS[col0 + 1];

            uint32_t afrag[2][4];
#pragma unroll
            for (int q = 0; q < 4; q++) {
                int4 av = adjb[m & 1][q];
                int ad0 = (s & 1) ? av.z : av.x;
                int ad1 = (s & 1) ? av.w : av.y;
                float t0 = f1r[q] + c0.x;
                float t1 = f1r[q] + c1.x;
                float p0 = (t0 > 0.f) ? e1r[q] * c0.y : e1br[q] * c0.z;
                float p1 = (t1 > 0.f) ? e1r[q] * c1.y : e1br[q] * c1.z;
                p0 = (ad0 != 0) ? p0 : 0.f;
                p1 = (ad1 != 0) ? p1 : 0.f;
                den[q] += p0 + p1;
                afrag[q >> 1][(q & 1) + 0] = f2tf32(p0);   // k-pos c   (u=0)
                afrag[q >> 1][(q & 1) + 2] = f2tf32(p1);   // k-pos c+4 (u=1)
            }

#pragma unroll
            for (int f = 0; f < 8; f++) {
                uint32_t boff = ((s * 8 + f) * 32 + lane) * 2;
                uint32_t b0 = bS[boff];
                uint32_t b1 = bS[boff + 1];
                mma_tf32(acc[0][f][0], acc[0][f][1], acc[0][f][2], acc[0][f][3],
                         afrag[0][0], afrag[0][1], afrag[0][2], afrag[0][3], b0, b1);
                mma_tf32(acc[1][f][0], acc[1][f][1], acc[1][f][2], acc[1][f][3],
                         afrag[1][0], afrag[1][1], afrag[1][2], afrag[1][3], b0, b1);
            }
        }

        __syncthreads();
        if (ck + 2 < ck1) prefetch(ck + 2, buf);
        CP_COMMIT();
    }

    // ---- epilogue: numerators ----
#pragma unroll
    for (int rf = 0; rf < 2; rf++) {
        int m0 = row0 + wid * 32 + rf * 16 + g;
#pragma unroll
        for (int f = 0; f < 8; f++) {
            int col = f * 8 + c * 2;
            *(float2*)&g_num[split][(size_t)m0 * OUTF + col] =
                make_float2(acc[rf][f][0], acc[rf][f][1]);
            *(float2*)&g_num[split][(size_t)(m0 + 8) * OUTF + col] =
                make_float2(acc[rf][f][2], acc[rf][f][3]);
        }
    }

    // ---- denominators: reduce over the quad (lanes sharing g) ----
#pragma unroll
    for (int q = 0; q < 4; q++) {
        den[q] += __shfl_xor_sync(0xFFFFFFFF, den[q], 1);
        den[q] += __shfl_xor_sync(0xFFFFFFFF, den[q], 2);
    }
    if (c == 0) {
#pragma unroll
        for (int q = 0; q < 4; q++)
            g_den[split][row0 + wid * 32 + g + q * 8] = den[q];
    }
}

// ---------------- combine partials, divide, elu ----------------
__global__ void __launch_bounds__(256) k_comb(float* __restrict__ out) {
    int idx = blockIdx.x * 256 + threadIdx.x;  // over NN*OUTF
    int row = idx >> 6;
    float num = 0.f, den = 0.f;
#pragma unroll
    for (int p = 0; p < NPART; p++) {
        num += g_num[p][idx];
        den += g_den[p][row];
    }
    float v = num / den;
    out[idx] = v > 0.f ? v : expm1f(v);
}

// ---------------- launch ----------------
#define PRE_SMEM (INF_ * OUTF * 4 + 32 * INF_ * 4 + 2 * OUTF * 4)  // 49664

extern "C" void kernel_launch(void* const* d_in, const int* in_sizes, int n_in,
                              void* d_out, int out_size) {
    const float* X = (const float*)d_in[0];
    const int* adj = (const int*)d_in[1];
    const float* W = (const float*)d_in[2];
    const float* a = (const float*)d_in[3];
    float* out = (float*)d_out;

    cudaFuncSetAttribute(k_pre, cudaFuncAttributeMaxDynamicSharedMemorySize, PRE_SMEM);
    cudaFuncSetAttribute(k_main, cudaFuncAttributeMaxDynamicSharedMemorySize, SMEM_BYTES);

    k_pre<<<NN / 32, 256, PRE_SMEM>>>(X, W, a);
    k_main<<<64 * NSPLIT, 128, SMEM_BYTES>>>(adj);
    k_comb<<<(NN * OUTF) / 256, 256>>>(out);
}

// round 13
// speedup vs baseline: 1.3994x; 1.3994x over previous
#include <cuda_runtime.h>
#include <cuda_bf16.h>
#include <cstdint>
#include <math.h>

// ---------------- problem constants ----------------
#define NN 8192
#define INF_ 128
#define OUTF 64

// grid decomposition for k_main
#define M_CTA 128        // rows per CTA
#define NSPLIT 7         // K splits (grid 64*7 = 448 ~= 148 SMs * 3)
#define NPART 7
#define KCHUNK 32        // cols per chunk
#define TOTCHUNK (NN / KCHUNK)   // 256

// ---------------- device scratch (no allocs allowed) ----------------
__device__ float4 g_rowf[NN];                       // (f1, e^f1, e^{0.2 f1}, 0)
__device__ float4 g_colf[NN];                       // (f2, e^{f2}, e^{0.2 f2}, 0)
__device__ uint32_t g_Bf[NN * OUTF];                // 2 MB  Ht tf32, B-frag order per 32-chunk
__device__ float g_num[NPART][NN * OUTF];           // 14 MB partial numerators
__device__ float g_den[NPART][NN];                  // partial denominators

// ---------------- smem layout for k_main ----------------
#define ADJ_STRIDE 144                     // bytes per adj row (32 ints + 16B pad)
#define ADJ_BYTES (M_CTA * ADJ_STRIDE)     // 18432
#define OFF_ADJ0 0
#define OFF_ADJ1 18432
#define OFF_BF0  36864                     // 8192 each: [s(4)][f(8)][lane][2] tf32
#define OFF_BF1  45056
#define OFF_CF0  53248                     // 512 each: 32 x float4 col factors
#define OFF_CF1  53760
#define SMEM_BYTES 54272

// ---------------- helpers ----------------
__device__ __forceinline__ uint32_t smem_u32(const void* p) {
    uint32_t a;
    asm("{ .reg .u64 t; cvta.to.shared.u64 t, %1; cvt.u32.u64 %0, t; }" : "=r"(a) : "l"(p));
    return a;
}
#define CP16(dst, src) \
    asm volatile("cp.async.cg.shared.global [%0], [%1], 16;" :: "r"(dst), "l"(src) : "memory")
#define CP_COMMIT() asm volatile("cp.async.commit_group;" ::: "memory")
#define CP_WAIT1()  asm volatile("cp.async.wait_group 1;" ::: "memory")

__device__ __forceinline__ uint32_t f2tf32(float x) {
    uint32_t r;
    asm("cvt.rna.tf32.f32 %0, %1;" : "=r"(r) : "f"(x));
    return r;
}
__device__ __forceinline__ void mma_tf32(float& d0, float& d1, float& d2, float& d3,
                                         uint32_t a0, uint32_t a1, uint32_t a2, uint32_t a3,
                                         uint32_t b0, uint32_t b1) {
    asm volatile("mma.sync.aligned.m16n8k8.row.col.f32.tf32.tf32.f32 "
                 "{%0,%1,%2,%3}, {%4,%5,%6,%7}, {%8,%9}, {%0,%1,%2,%3};"
                 : "+f"(d0), "+f"(d1), "+f"(d2), "+f"(d3)
                 : "r"(a0), "r"(a1), "r"(a2), "r"(a3), "r"(b0), "r"(b1));
}

// ---------------- fused pre-pass: h = X@W, per-node factors, B fragments ----------------
// grid 256 x 32 rows, 256 threads: 16 threads per row-pair (rows r, r+16), 4 cols each.
// B-frag layout per 32-col chunk: word ((s*8+f)*32 + l)*2 + half, where for h-row j:
// chunk=j>>5, jl=j&31, s=jl>>3, p=jl&7, half=p>>2, l=((n&7)<<2)|(p&3).
__global__ void __launch_bounds__(256) k_pre(const float* __restrict__ X,
                                             const float* __restrict__ W,
                                             const float* __restrict__ a) {
    extern __shared__ float dsm[];
    float* Ws = dsm;                    // [128*64]  32 KB
    float* Xs = dsm + INF_ * OUTF;      // [32*128]  16 KB
    float* as = Xs + 32 * INF_;         // [128]     512 B

    int tid = threadIdx.x;
    const float4* W4 = (const float4*)W;
    float4* Ws4 = (float4*)Ws;
#pragma unroll
    for (int q = 0; q < 8; q++) Ws4[tid + q * 256] = W4[tid + q * 256];
    int r0 = blockIdx.x * 32;
    const float4* X4 = (const float4*)(X + (size_t)r0 * INF_);
    float4* Xs4 = (float4*)Xs;
#pragma unroll
    for (int q = 0; q < 4; q++) Xs4[tid + q * 256] = X4[tid + q * 256];
    if (tid < 128) as[tid] = a[tid];
    __syncthreads();

    int r = tid >> 4;                 // 0..15 -> rows r and r+16
    int cg = (tid & 15) * 4;          // cols cg..cg+3
    int wcol = cg >> 2;               // 0..15 float4 column of W
    float acc0[4], acc1[4];
#pragma unroll
    for (int j = 0; j < 4; j++) { acc0[j] = 0.f; acc1[j] = 0.f; }

    const float4* Xs4v = (const float4*)Xs;
    const float4* Ws4v = (const float4*)Ws;
#pragma unroll 4
    for (int k4 = 0; k4 < 32; k4++) {
        float4 x0 = Xs4v[r * 32 + k4];
        float4 x1 = Xs4v[(r + 16) * 32 + k4];
        float4 w;
        w = Ws4v[(k4 * 4 + 0) * 16 + wcol];
        acc0[0] += x0.x * w.x; acc0[1] += x0.x * w.y; acc0[2] += x0.x * w.z; acc0[3] += x0.x * w.w;
        acc1[0] += x1.x * w.x; acc1[1] += x1.x * w.y; acc1[2] += x1.x * w.z; acc1[3] += x1.x * w.w;
        w = Ws4v[(k4 * 4 + 1) * 16 + wcol];
        acc0[0] += x0.y * w.x; acc0[1] += x0.y * w.y; acc0[2] += x0.y * w.z; acc0[3] += x0.y * w.w;
        acc1[0] += x1.y * w.x; acc1[1] += x1.y * w.y; acc1[2] += x1.y * w.z; acc1[3] += x1.y * w.w;
        w = Ws4v[(k4 * 4 + 2) * 16 + wcol];
        acc0[0] += x0.z * w.x; acc0[1] += x0.z * w.y; acc0[2] += x0.z * w.z; acc0[3] += x0.z * w.w;
        acc1[0] += x1.z * w.x; acc1[1] += x1.z * w.y; acc1[2] += x1.z * w.z; acc1[3] += x1.z * w.w;
        w = Ws4v[(k4 * 4 + 3) * 16 + wcol];
        acc0[0] += x0.w * w.x; acc0[1] += x0.w * w.y; acc0[2] += x0.w * w.z; acc0[3] += x0.w * w.w;
        acc1[0] += x1.w * w.x; acc1[1] += x1.w * w.y; acc1[2] += x1.w * w.z; acc1[3] += x1.w * w.w;
    }

    // f1/f2 for both rows, reduced over the 16 threads of each row
    float f1a = 0.f, f2a = 0.f, f1b = 0.f, f2b = 0.f;
#pragma unroll
    for (int j = 0; j < 4; j++) {
        f1a += acc0[j] * as[cg + j];  f2a += acc0[j] * as[64 + cg + j];
        f1b += acc1[j] * as[cg + j];  f2b += acc1[j] * as[64 + cg + j];
    }
#pragma unroll
    for (int o = 8; o > 0; o >>= 1) {
        f1a += __shfl_xor_sync(0xFFFFFFFF, f1a, o);
        f2a += __shfl_xor_sync(0xFFFFFFFF, f2a, o);
        f1b += __shfl_xor_sync(0xFFFFFFFF, f1b, o);
        f2b += __shfl_xor_sync(0xFFFFFFFF, f2b, o);
    }
    int rowA = r0 + r, rowB = r0 + r + 16;
    if ((tid & 15) == 0) {
        g_rowf[rowA] = make_float4(f1a, expf(f1a), expf(0.2f * f1a), 0.f);
        g_colf[rowA] = make_float4(f2a, expf(f2a), expf(0.2f * f2a), 0.f);
        g_rowf[rowB] = make_float4(f1b, expf(f1b), expf(0.2f * f1b), 0.f);
        g_colf[rowB] = make_float4(f2b, expf(f2b), expf(0.2f * f2b), 0.f);
    }

    // scatter B fragments (chunk-32 layout)
#pragma unroll
    for (int pass = 0; pass < 2; pass++) {
        int row = pass ? rowB : rowA;
        const float* av = pass ? acc1 : acc0;
        int chunk = row >> 5;
        int jl = row & 31;
        int ss = jl >> 3;
        int p = jl & 7;
        int half = p >> 2;
        int l_lo = p & 3;
#pragma unroll
        for (int j = 0; j < 4; j++) {
            int n = cg + j;
            int f = n >> 3;
            int l = ((n & 7) << 2) | l_lo;
            g_Bf[(size_t)chunk * 2048 + (((ss * 8 + f) * 32 + l) << 1) + half] = f2tf32(av[j]);
        }
    }
}

// ---------------- main kernel ----------------
// grid 448 x 128 threads: rb = blockIdx % 64 (row block of 128), split = blockIdx / 64.
// 4 warps x 32 rows; 32-col chunks double-buffered via cp.async; 3 CTAs/SM.
__global__ void __launch_bounds__(128, 3) k_main(const int* __restrict__ adj) {
    extern __shared__ char sm[];
    uint32_t sb = smem_u32(sm);

    int tid = threadIdx.x;
    int wid = tid >> 5;     // 0..3
    int lane = tid & 31;
    int g = lane >> 2;
    int c = lane & 3;

    int rb = blockIdx.x & 63;
    int split = blockIdx.x >> 6;     // 0..6
    int row0 = rb * M_CTA;
    int ck0 = (split * TOTCHUNK) / NSPLIT;
    int ck1 = ((split + 1) * TOTCHUNK) / NSPLIT;

    // row factors for this thread's 4 rows (g + 8q within warp's 32)
    float f1r[4], e1r[4], e1br[4];
#pragma unroll
    for (int q = 0; q < 4; q++) {
        float4 rf = g_rowf[row0 + wid * 32 + g + q * 8];
        f1r[q] = rf.x; e1r[q] = rf.y; e1br[q] = rf.z;
    }

    float acc[2][8][4];
#pragma unroll
    for (int i = 0; i < 2; i++)
#pragma unroll
        for (int f = 0; f < 8; f++)
#pragma unroll
            for (int q = 0; q < 4; q++) acc[i][f][q] = 0.f;

    float den[4] = {0.f, 0.f, 0.f, 0.f};

    const uint32_t adjOff[2] = {OFF_ADJ0, OFF_ADJ1};
    const uint32_t bfOff[2] = {OFF_BF0, OFF_BF1};
    const uint32_t cfOff[2] = {OFF_CF0, OFF_CF1};

    auto prefetch = [&](int ck, int buf) {
        int K0 = ck * KCHUNK;
        // adj: 128 rows x 32 ints = 8 granules of 16B per row, 128 threads
        int jr = tid & 7;
        int rbase = tid >> 3;       // 0..15
        const char* srcbase = (const char*)(adj + (size_t)row0 * NN + K0) + jr * 16;
        uint32_t dstbase = sb + adjOff[buf] + jr * 16;
#pragma unroll
        for (int pass = 0; pass < 8; pass++) {
            int row = pass * 16 + rbase;
            CP16(dstbase + row * ADJ_STRIDE, srcbase + (size_t)row * (NN * 4));
        }
        // B fragments: 8 KB contiguous at g_Bf byte offset ck*8192
        const char* bsrc = (const char*)g_Bf + (size_t)ck * 8192;
        uint32_t bdst = sb + bfOff[buf];
#pragma unroll
        for (int p = 0; p < 4; p++) {
            int piece = tid + p * 128;
            CP16(bdst + piece * 16, bsrc + piece * 16);
        }
        // col factors: 32 x float4
        if (tid < 32) {
            CP16(sb + cfOff[buf] + tid * 16, (const char*)(g_colf + K0 + tid));
        }
    };

    prefetch(ck0, 0); CP_COMMIT();
    prefetch(ck0 + 1, 1); CP_COMMIT();

    for (int ck = ck0; ck < ck1; ++ck) {
        int buf = (ck - ck0) & 1;
        CP_WAIT1();
        __syncthreads();

        const char* adjS = sm + adjOff[buf];
        const uint32_t* bS = (const uint32_t*)(sm + bfOff[buf]);
        const float4* cfS = (const float4*)(sm + cfOff[buf]);

#pragma unroll
        for (int s = 0; s < 4; s++) {
            float4 c0 = cfS[s * 8 + c];
            float4 c4 = cfS[s * 8 + c + 4];

            uint32_t afrag[2][4];
#pragma unroll
            for (int q = 0; q < 4; q++) {     // q -> row g + 8q
                int row = wid * 32 + g + q * 8;
                const int* arow = (const int*)(adjS + row * ADJ_STRIDE) + s * 8 + c;
                int ad0 = arow[0];
                int ad4 = arow[4];
                float t0 = f1r[q] + c0.x;
                float t4 = f1r[q] + c4.x;
                float p0 = (t0 > 0.f) ? e1r[q] * c0.y : e1br[q] * c0.z;
                float p4 = (t4 > 0.f) ? e1r[q] * c4.y : e1br[q] * c4.z;
                p0 = (ad0 != 0) ? p0 : 0.f;
                p4 = (ad4 != 0) ? p4 : 0.f;
                den[q] += p0 + p4;
                afrag[q >> 1][(q & 1) + 0] = f2tf32(p0);
                afrag[q >> 1][(q & 1) + 2] = f2tf32(p4);
            }

#pragma unroll
            for (int f = 0; f < 8; f++) {
                uint32_t boff = ((s * 8 + f) * 32 + lane) * 2;
                uint32_t b0 = bS[boff];
                uint32_t b1 = bS[boff + 1];
                mma_tf32(acc[0][f][0], acc[0][f][1], acc[0][f][2], acc[0][f][3],
                         afrag[0][0], afrag[0][1], afrag[0][2], afrag[0][3], b0, b1);
                mma_tf32(acc[1][f][0], acc[1][f][1], acc[1][f][2], acc[1][f][3],
                         afrag[1][0], afrag[1][1], afrag[1][2], afrag[1][3], b0, b1);
            }
        }

        __syncthreads();
        if (ck + 2 < ck1) prefetch(ck + 2, buf);
        CP_COMMIT();
    }

    // ---- epilogue: numerators ----
#pragma unroll
    for (int rf = 0; rf < 2; rf++) {
        int m0 = row0 + wid * 32 + rf * 16 + g;
#pragma unroll
        for (int f = 0; f < 8; f++) {
            int col = f * 8 + c * 2;
            *(float2*)&g_num[split][(size_t)m0 * OUTF + col] =
                make_float2(acc[rf][f][0], acc[rf][f][1]);
            *(float2*)&g_num[split][(size_t)(m0 + 8) * OUTF + col] =
                make_float2(acc[rf][f][2], acc[rf][f][3]);
        }
    }

    // ---- denominators: reduce over the quad (lanes sharing g) ----
#pragma unroll
    for (int q = 0; q < 4; q++) {
        den[q] += __shfl_xor_sync(0xFFFFFFFF, den[q], 1);
        den[q] += __shfl_xor_sync(0xFFFFFFFF, den[q], 2);
    }
    if (c == 0) {
#pragma unroll
        for (int q = 0; q < 4; q++)
            g_den[split][row0 + wid * 32 + g + q * 8] = den[q];
    }
}

// ---------------- combine partials, divide, elu ----------------
__global__ void __launch_bounds__(256) k_comb(float* __restrict__ out) {
    int idx = blockIdx.x * 256 + threadIdx.x;  // over NN*OUTF
    int row = idx >> 6;
    float num = 0.f, den = 0.f;
#pragma unroll
    for (int p = 0; p < NPART; p++) {
        num += g_num[p][idx];
        den += g_den[p][row];
    }
    float v = num / den;
    out[idx] = v > 0.f ? v : expm1f(v);
}

// ---------------- launch ----------------
#define PRE_SMEM (INF_ * OUTF * 4 + 32 * INF_ * 4 + 2 * OUTF * 4)  // 49664

extern "C" void kernel_launch(void* const* d_in, const int* in_sizes, int n_in,
                              void* d_out, int out_size) {
    const float* X = (const float*)d_in[0];
    const int* adj = (const int*)d_in[1];
    const float* W = (const float*)d_in[2];
    const float* a = (const float*)d_in[3];
    float* out = (float*)d_out;

    cudaFuncSetAttribute(k_pre, cudaFuncAttributeMaxDynamicSharedMemorySize, PRE_SMEM);
    cudaFuncSetAttribute(k_main, cudaFuncAttributeMaxDynamicSharedMemorySize, SMEM_BYTES);

    k_pre<<<NN / 32, 256, PRE_SMEM>>>(X, W, a);
    k_main<<<64 * NSPLIT, 128, SMEM_BYTES>>>(adj);
    k_comb<<<(NN * OUTF) / 256, 256>>>(out);
}

// round 15
// speedup vs baseline: 1.5465x; 1.1051x over previous
#include <cuda_runtime.h>
#include <cuda_bf16.h>
#include <cstdint>
#include <math.h>

// ---------------- problem constants ----------------
#define NN 8192
#define INF_ 128
#define OUTF 64

// grid decomposition for k_main
#define M_CTA 128        // rows per CTA
#define NSPLIT 4         // K splits
#define KSPLIT (NN / NSPLIT)   // 2048 cols per CTA
#define KCHUNK 64        // cols per chunk
#define NCHUNK (KSPLIT / KCHUNK) // 32

// ---------------- device scratch (no allocs allowed) ----------------
__device__ float4 g_rowf[NN];                       // (f1, e^f1, e^{0.2 f1}, 0)
__device__ float4 g_colf[NN];                       // (f2, e^{f2}, e^{0.2 f2}, 0)
__device__ uint32_t g_Bf[NN * OUTF];                // 2 MB  Ht tf32, B-fragment order
__device__ float g_num[NSPLIT][NN * OUTF];          // 8 MB  partial numerators
__device__ float g_den[NSPLIT][NN];                 // partial denominators

// ---------------- smem layout for k_main ----------------
#define ADJ_STRIDE 272                     // bytes per adj row (64 ints + pad)
#define OFF_ADJ0 0
#define OFF_ADJ1 34816
#define OFF_BF0  69632                     // 16384 each: [s][f][lane][2] tf32
#define OFF_BF1  86016
#define OFF_CF0  102400                    // 1024 each: 64 x float4 col factors
#define OFF_CF1  103424
#define SMEM_BYTES 104448

// ---------------- helpers ----------------
__device__ __forceinline__ uint32_t smem_u32(const void* p) {
    uint32_t a;
    asm("{ .reg .u64 t; cvta.to.shared.u64 t, %1; cvt.u32.u64 %0, t; }" : "=r"(a) : "l"(p));
    return a;
}
#define CP16(dst, src) \
    asm volatile("cp.async.cg.shared.global [%0], [%1], 16;" :: "r"(dst), "l"(src) : "memory")
#define CP_COMMIT() asm volatile("cp.async.commit_group;" ::: "memory")
#define CP_WAIT1()  asm volatile("cp.async.wait_group 1;" ::: "memory")

__device__ __forceinline__ uint32_t f2tf32(float x) {
    uint32_t r;
    asm("cvt.rna.tf32.f32 %0, %1;" : "=r"(r) : "f"(x));
    return r;
}
__device__ __forceinline__ void mma_tf32(float& d0, float& d1, float& d2, float& d3,
                                         uint32_t a0, uint32_t a1, uint32_t a2, uint32_t a3,
                                         uint32_t b0, uint32_t b1) {
    asm volatile("mma.sync.aligned.m16n8k8.row.col.f32.tf32.tf32.f32 "
                 "{%0,%1,%2,%3}, {%4,%5,%6,%7}, {%8,%9}, {%0,%1,%2,%3};"
                 : "+f"(d0), "+f"(d1), "+f"(d2), "+f"(d3)
                 : "r"(a0), "r"(a1), "r"(a2), "r"(a3), "r"(b0), "r"(b1));
}

// ---------------- fused pre-pass: h = X@W, per-node factors, B fragments ----------------
// grid 256 x 32 rows, 256 threads: 16 threads per row-pair (rows r, r+16), 4 cols each.
__global__ void __launch_bounds__(256) k_pre(const float* __restrict__ X,
                                             const float* __restrict__ W,
                                             const float* __restrict__ a) {
    extern __shared__ float dsm[];
    float* Ws = dsm;                    // [128*64]  32 KB
    float* Xs = dsm + INF_ * OUTF;      // [32*128]  16 KB
    float* as = Xs + 32 * INF_;         // [128]     512 B

    int tid = threadIdx.x;
    const float4* W4 = (const float4*)W;
    float4* Ws4 = (float4*)Ws;
#pragma unroll
    for (int q = 0; q < 8; q++) Ws4[tid + q * 256] = W4[tid + q * 256];
    int r0 = blockIdx.x * 32;
    const float4* X4 = (const float4*)(X + (size_t)r0 * INF_);
    float4* Xs4 = (float4*)Xs;
#pragma unroll
    for (int q = 0; q < 4; q++) Xs4[tid + q * 256] = X4[tid + q * 256];
    if (tid < 128) as[tid] = a[tid];
    __syncthreads();

    int r = tid >> 4;                 // 0..15 -> rows r and r+16
    int cg = (tid & 15) * 4;          // cols cg..cg+3
    int wcol = cg >> 2;
    float acc0[4], acc1[4];
#pragma unroll
    for (int j = 0; j < 4; j++) { acc0[j] = 0.f; acc1[j] = 0.f; }

    const float4* Xs4v = (const float4*)Xs;
    const float4* Ws4v = (const float4*)Ws;
#pragma unroll 4
    for (int k4 = 0; k4 < 32; k4++) {
        float4 x0 = Xs4v[r * 32 + k4];
        float4 x1 = Xs4v[(r + 16) * 32 + k4];
        float4 w;
        w = Ws4v[(k4 * 4 + 0) * 16 + wcol];
        acc0[0] += x0.x * w.x; acc0[1] += x0.x * w.y; acc0[2] += x0.x * w.z; acc0[3] += x0.x * w.w;
        acc1[0] += x1.x * w.x; acc1[1] += x1.x * w.y; acc1[2] += x1.x * w.z; acc1[3] += x1.x * w.w;
        w = Ws4v[(k4 * 4 + 1) * 16 + wcol];
        acc0[0] += x0.y * w.x; acc0[1] += x0.y * w.y; acc0[2] += x0.y * w.z; acc0[3] += x0.y * w.w;
        acc1[0] += x1.y * w.x; acc1[1] += x1.y * w.y; acc1[2] += x1.y * w.z; acc1[3] += x1.y * w.w;
        w = Ws4v[(k4 * 4 + 2) * 16 + wcol];
        acc0[0] += x0.z * w.x; acc0[1] += x0.z * w.y; acc0[2] += x0.z * w.z; acc0[3] += x0.z * w.w;
        acc1[0] += x1.z * w.x; acc1[1] += x1.z * w.y; acc1[2] += x1.z * w.z; acc1[3] += x1.z * w.w;
        w = Ws4v[(k4 * 4 + 3) * 16 + wcol];
        acc0[0] += x0.w * w.x; acc0[1] += x0.w * w.y; acc0[2] += x0.w * w.z; acc0[3] += x0.w * w.w;
        acc1[0] += x1.w * w.x; acc1[1] += x1.w * w.y; acc1[2] += x1.w * w.z; acc1[3] += x1.w * w.w;
    }

    float f1a = 0.f, f2a = 0.f, f1b = 0.f, f2b = 0.f;
#pragma unroll
    for (int j = 0; j < 4; j++) {
        f1a += acc0[j] * as[cg + j];  f2a += acc0[j] * as[64 + cg + j];
        f1b += acc1[j] * as[cg + j];  f2b += acc1[j] * as[64 + cg + j];
    }
#pragma unroll
    for (int o = 8; o > 0; o >>= 1) {
        f1a += __shfl_xor_sync(0xFFFFFFFF, f1a, o);
        f2a += __shfl_xor_sync(0xFFFFFFFF, f2a, o);
        f1b += __shfl_xor_sync(0xFFFFFFFF, f1b, o);
        f2b += __shfl_xor_sync(0xFFFFFFFF, f2b, o);
    }
    int rowA = r0 + r, rowB = r0 + r + 16;
    if ((tid & 15) == 0) {
        g_rowf[rowA] = make_float4(f1a, expf(f1a), expf(0.2f * f1a), 0.f);
        g_colf[rowA] = make_float4(f2a, expf(f2a), expf(0.2f * f2a), 0.f);
        g_rowf[rowB] = make_float4(f1b, expf(f1b), expf(0.2f * f1b), 0.f);
        g_colf[rowB] = make_float4(f2b, expf(f2b), expf(0.2f * f2b), 0.f);
    }

    // scatter B fragments (global-s layout): h[row][n] -> g_Bf[((s*8+f)*32+l)*2+half]
#pragma unroll
    for (int pass = 0; pass < 2; pass++) {
        int row = pass ? rowB : rowA;
        const float* av = pass ? acc1 : acc0;
        int s = row >> 3;
        int l_lo = row & 3;
        int half = (row >> 2) & 1;
#pragma unroll
        for (int j = 0; j < 4; j++) {
            int n = cg + j;
            int f = n >> 3;
            int l = ((n & 7) << 2) | l_lo;
            g_Bf[(((size_t)(s * 8 + f) * 32 + l) << 1) + half] = f2tf32(av[j]);
        }
    }
}

// ---------------- main kernel ----------------
// grid 256 x 128 threads: rb = blockIdx & 63 (row block of 128), split = blockIdx >> 6.
// 4 warps x 32 rows. Inner s-loop is register-software-pipelined: all LDS for
// step s+1 issued before the compute of step s (kills short-scoreboard stalls).
__global__ void __launch_bounds__(128, 2) k_main(const int* __restrict__ adj) {
    extern __shared__ char sm[];
    uint32_t sb = smem_u32(sm);

    int tid = threadIdx.x;
    int wid = tid >> 5;     // 0..3
    int lane = tid & 31;
    int g = lane >> 2;
    int c = lane & 3;

    int rb = blockIdx.x & 63;
    int split = blockIdx.x >> 6;
    int row0 = rb * M_CTA;
    int K0base = split * KSPLIT;

    float f1r[4], e1r[4], e1br[4];
#pragma unroll
    for (int q = 0; q < 4; q++) {
        float4 rf = g_rowf[row0 + wid * 32 + g + q * 8];
        f1r[q] = rf.x; e1r[q] = rf.y; e1br[q] = rf.z;
    }

    float acc[2][8][4];
#pragma unroll
    for (int i = 0; i < 2; i++)
#pragma unroll
        for (int f = 0; f < 8; f++)
#pragma unroll
            for (int q = 0; q < 4; q++) acc[i][f][q] = 0.f;

    float den[4] = {0.f, 0.f, 0.f, 0.f};

    const uint32_t adjOff[2] = {OFF_ADJ0, OFF_ADJ1};
    const uint32_t bfOff[2] = {OFF_BF0, OFF_BF1};
    const uint32_t cfOff[2] = {OFF_CF0, OFF_CF1};

    auto prefetch = [&](int chunk, int buf) {
        int K0 = K0base + chunk * KCHUNK;
        int jr = tid & 15;
        int rbase = tid >> 4;       // 0..7
        const char* srcbase = (const char*)(adj + (size_t)row0 * NN + K0) + jr * 16;
        uint32_t dstbase = sb + adjOff[buf] + jr * 16;
#pragma unroll
        for (int pass = 0; pass < 16; pass++) {
            int row = pass * 8 + rbase;
            CP16(dstbase + row * ADJ_STRIDE, srcbase + (size_t)row * (NN * 4));
        }
        const char* bsrc = (const char*)g_Bf + (size_t)K0 * 256;
        uint32_t bdst = sb + bfOff[buf];
#pragma unroll
        for (int p = 0; p < 8; p++) {
            int piece = tid + p * 128;
            CP16(bdst + piece * 16, bsrc + piece * 16);
        }
        if (tid < 64) {
            CP16(sb + cfOff[buf] + tid * 16, (const char*)(g_colf + K0 + tid));
        }
    };

    prefetch(0, 0); CP_COMMIT();
    prefetch(1, 1); CP_COMMIT();

    for (int it = 0; it < NCHUNK; ++it) {
        int buf = it & 1;
        CP_WAIT1();
        __syncthreads();

        const char* adjS = sm + adjOff[buf];
        const uint32_t* bS = (const uint32_t*)(sm + bfOff[buf]);
        const float4* cfS = (const float4*)(sm + cfOff[buf]);

        // ---- register software pipeline: stage s+1 loads ahead of s compute ----
        float4 rc0[2], rc4[2];
        int ra[2][8];
        uint32_t rbf[2][16];

        // prologue: stage s = 0
        rc0[0] = cfS[c];
        rc4[0] = cfS[c + 4];
#pragma unroll
        for (int q = 0; q < 4; q++) {
            int row = wid * 32 + g + q * 8;
            const int* ar = (const int*)(adjS + row * ADJ_STRIDE) + c;
            ra[0][2 * q] = ar[0];
            ra[0][2 * q + 1] = ar[4];
        }
#pragma unroll
        for (int f = 0; f < 8; f++) {
            uint32_t boff = (f * 32 + lane) * 2;
            rbf[0][2 * f] = bS[boff];
            rbf[0][2 * f + 1] = bS[boff + 1];
        }

#pragma unroll
        for (int s = 0; s < 8; s++) {
            int cur = s & 1, nxt = cur ^ 1;
            if (s < 7) {
                rc0[nxt] = cfS[(s + 1) * 8 + c];
                rc4[nxt] = cfS[(s + 1) * 8 + c + 4];
#pragma unroll
                for (int q = 0; q < 4; q++) {
                    int row = wid * 32 + g + q * 8;
                    const int* ar = (const int*)(adjS + row * ADJ_STRIDE) + (s + 1) * 8 + c;
                    ra[nxt][2 * q] = ar[0];
                    ra[nxt][2 * q + 1] = ar[4];
                }
#pragma unroll
                for (int f = 0; f < 8; f++) {
                    uint32_t boff = (((s + 1) * 8 + f) * 32 + lane) * 2;
                    rbf[nxt][2 * f] = bS[boff];
                    rbf[nxt][2 * f + 1] = bS[boff + 1];
                }
            }

            float4 c0 = rc0[cur], c4 = rc4[cur];
            uint32_t afrag[2][4];
#pragma unroll
            for (int q = 0; q < 4; q++) {
                int ad0 = ra[cur][2 * q];
                int ad4 = ra[cur][2 * q + 1];
                float t0 = f1r[q] + c0.x;
                float t4 = f1r[q] + c4.x;
                float p0 = (t0 > 0.f) ? e1r[q] * c0.y : e1br[q] * c0.z;
                float p4 = (t4 > 0.f) ? e1r[q] * c4.y : e1br[q] * c4.z;
                p0 = (ad0 != 0) ? p0 : 0.f;
                p4 = (ad4 != 0) ? p4 : 0.f;
                den[q] += p0 + p4;
                afrag[q >> 1][(q & 1) + 0] = f2tf32(p0);
                afrag[q >> 1][(q & 1) + 2] = f2tf32(p4);
            }

#pragma unroll
            for (int f = 0; f < 8; f++) {
                uint32_t b0 = rbf[cur][2 * f];
                uint32_t b1 = rbf[cur][2 * f + 1];
                mma_tf32(acc[0][f][0], acc[0][f][1], acc[0][f][2], acc[0][f][3],
                         afrag[0][0], afrag[0][1], afrag[0][2], afrag[0][3], b0, b1);
                mma_tf32(acc[1][f][0], acc[1][f][1], acc[1][f][2], acc[1][f][3],
                         afrag[1][0], afrag[1][1], afrag[1][2], afrag[1][3], b0, b1);
            }
        }

        __syncthreads();
        if (it + 2 < NCHUNK) prefetch(it + 2, buf);
        CP_COMMIT();
    }

    // ---- epilogue: numerators ----
#pragma unroll
    for (int rf = 0; rf < 2; rf++) {
        int m0 = row0 + wid * 32 + rf * 16 + g;
#pragma unroll
        for (int f = 0; f < 8; f++) {
            int col = f * 8 + c * 2;
            *(float2*)&g_num[split][(size_t)m0 * OUTF + col] =
                make_float2(acc[rf][f][0], acc[rf][f][1]);
            *(float2*)&g_num[split][(size_t)(m0 + 8) * OUTF + col] =
                make_float2(acc[rf][f][2], acc[rf][f][3]);
        }
    }

    // ---- denominators: reduce over the quad (lanes sharing g) ----
#pragma unroll
    for (int q = 0; q < 4; q++) {
        den[q] += __shfl_xor_sync(0xFFFFFFFF, den[q], 1);
        den[q] += __shfl_xor_sync(0xFFFFFFFF, den[q], 2);
    }
    if (c == 0) {
#pragma unroll
        for (int q = 0; q < 4; q++)
            g_den[split][row0 + wid * 32 + g + q * 8] = den[q];
    }
}

// ---------------- combine partials, divide, elu ----------------
__global__ void __launch_bounds__(256) k_comb(float* __restrict__ out) {
    int idx = blockIdx.x * 256 + threadIdx.x;  // over NN*OUTF
    int row = idx >> 6;
    float num = 0.f, den = 0.f;
#pragma unroll
    for (int p = 0; p < NSPLIT; p++) {
        num += g_num[p][idx];
        den += g_den[p][row];
    }
    float v = num / den;
    out[idx] = v > 0.f ? v : expm1f(v);
}

// ---------------- launch ----------------
#define PRE_SMEM (INF_ * OUTF * 4 + 32 * INF_ * 4 + 2 * OUTF * 4)  // 49664

extern "C" void kernel_launch(void* const* d_in, const int* in_sizes, int n_in,
                              void* d_out, int out_size) {
    const float* X = (const float*)d_in[0];
    const int* adj = (const int*)d_in[1];
    const float* W = (const float*)d_in[2];
    const float* a = (const float*)d_in[3];
    float* out = (float*)d_out;

    cudaFuncSetAttribute(k_pre, cudaFuncAttributeMaxDynamicSharedMemorySize, PRE_SMEM);
    cudaFuncSetAttribute(k_main, cudaFuncAttributeMaxDynamicSharedMemorySize, SMEM_BYTES);

    k_pre<<<NN / 32, 256, PRE_SMEM>>>(X, W, a);
    k_main<<<256, 128, SMEM_BYTES>>>(adj);
    k_comb<<<(NN * OUTF) / 256, 256>>>(out);
}

// round 16
// speedup vs baseline: 1.6208x; 1.0481x over previous
#include <cuda_runtime.h>
#include <cuda_bf16.h>
#include <cstdint>
#include <math.h>

// ---------------- problem constants ----------------
#define NN 8192
#define INF_ 128
#define OUTF 64

// grid decomposition for k_main
#define M_CTA 128        // rows per CTA
#define NSPLIT 4         // K splits
#define KSPLIT (NN / NSPLIT)   // 2048 cols per CTA
#define KCHUNK 64        // cols per chunk
#define NCHUNK (KSPLIT / KCHUNK) // 32

// ---------------- device scratch (no allocs allowed) ----------------
__device__ float2 g_rowf[NN];                       // (e^f1, e^{0.2 f1})
__device__ float2 g_colf[NN];                       // (e^{f2}, e^{0.2 f2})
__device__ uint32_t g_Bf[NN * OUTF];                // 2 MB  Ht tf32, B-fragment order
__device__ float g_num[NSPLIT][NN * OUTF];          // 8 MB  partial numerators
__device__ float g_den[NSPLIT][NN];                 // partial denominators

// ---------------- smem layout for k_main ----------------
#define ADJ_STRIDE 272                     // bytes per adj row (64 ints + pad)
#define OFF_ADJ0 0
#define OFF_ADJ1 34816
#define OFF_BF0  69632                     // 16384 each: [s][f][lane][2] tf32
#define OFF_BF1  86016
#define OFF_CF0  102400                    // 512 each: 64 x float2 col factors
#define OFF_CF1  102912
#define SMEM_BYTES 103424

// ---------------- helpers ----------------
__device__ __forceinline__ uint32_t smem_u32(const void* p) {
    uint32_t a;
    asm("{ .reg .u64 t; cvta.to.shared.u64 t, %1; cvt.u32.u64 %0, t; }" : "=r"(a) : "l"(p));
    return a;
}
#define CP16(dst, src) \
    asm volatile("cp.async.cg.shared.global [%0], [%1], 16;" :: "r"(dst), "l"(src) : "memory")
#define CP_COMMIT() asm volatile("cp.async.commit_group;" ::: "memory")
#define CP_WAIT1()  asm volatile("cp.async.wait_group 1;" ::: "memory")

__device__ __forceinline__ uint32_t f2tf32(float x) {
    uint32_t r;
    asm("cvt.rna.tf32.f32 %0, %1;" : "=r"(r) : "f"(x));
    return r;
}
__device__ __forceinline__ void mma_tf32(float& d0, float& d1, float& d2, float& d3,
                                         uint32_t a0, uint32_t a1, uint32_t a2, uint32_t a3,
                                         uint32_t b0, uint32_t b1) {
    asm volatile("mma.sync.aligned.m16n8k8.row.col.f32.tf32.tf32.f32 "
                 "{%0,%1,%2,%3}, {%4,%5,%6,%7}, {%8,%9}, {%0,%1,%2,%3};"
                 : "+f"(d0), "+f"(d1), "+f"(d2), "+f"(d3)
                 : "r"(a0), "r"(a1), "r"(a2), "r"(a3), "r"(b0), "r"(b1));
}

// ---------------- fused pre-pass: h = X@W, per-node factors, B fragments ----------------
// grid 256 x 32 rows, 256 threads: 16 threads per row-pair (rows r, r+16), 4 cols each.
__global__ void __launch_bounds__(256) k_pre(const float* __restrict__ X,
                                             const float* __restrict__ W,
                                             const float* __restrict__ a) {
    extern __shared__ float dsm[];
    float* Ws = dsm;                    // [128*64]  32 KB
    float* Xs = dsm + INF_ * OUTF;      // [32*128]  16 KB
    float* as = Xs + 32 * INF_;         // [128]     512 B

    int tid = threadIdx.x;
    const float4* W4 = (const float4*)W;
    float4* Ws4 = (float4*)Ws;
#pragma unroll
    for (int q = 0; q < 8; q++) Ws4[tid + q * 256] = W4[tid + q * 256];
    int r0 = blockIdx.x * 32;
    const float4* X4 = (const float4*)(X + (size_t)r0 * INF_);
    float4* Xs4 = (float4*)Xs;
#pragma unroll
    for (int q = 0; q < 4; q++) Xs4[tid + q * 256] = X4[tid + q * 256];
    if (tid < 128) as[tid] = a[tid];
    __syncthreads();

    int r = tid >> 4;                 // 0..15 -> rows r and r+16
    int cg = (tid & 15) * 4;          // cols cg..cg+3
    int wcol = cg >> 2;
    float acc0[4], acc1[4];
#pragma unroll
    for (int j = 0; j < 4; j++) { acc0[j] = 0.f; acc1[j] = 0.f; }

    const float4* Xs4v = (const float4*)Xs;
    const float4* Ws4v = (const float4*)Ws;
#pragma unroll 4
    for (int k4 = 0; k4 < 32; k4++) {
        float4 x0 = Xs4v[r * 32 + k4];
        float4 x1 = Xs4v[(r + 16) * 32 + k4];
        float4 w;
        w = Ws4v[(k4 * 4 + 0) * 16 + wcol];
        acc0[0] += x0.x * w.x; acc0[1] += x0.x * w.y; acc0[2] += x0.x * w.z; acc0[3] += x0.x * w.w;
        acc1[0] += x1.x * w.x; acc1[1] += x1.x * w.y; acc1[2] += x1.x * w.z; acc1[3] += x1.x * w.w;
        w = Ws4v[(k4 * 4 + 1) * 16 + wcol];
        acc0[0] += x0.y * w.x; acc0[1] += x0.y * w.y; acc0[2] += x0.y * w.z; acc0[3] += x0.y * w.w;
        acc1[0] += x1.y * w.x; acc1[1] += x1.y * w.y; acc1[2] += x1.y * w.z; acc1[3] += x1.y * w.w;
        w = Ws4v[(k4 * 4 + 2) * 16 + wcol];
        acc0[0] += x0.z * w.x; acc0[1] += x0.z * w.y; acc0[2] += x0.z * w.z; acc0[3] += x0.z * w.w;
        acc1[0] += x1.z * w.x; acc1[1] += x1.z * w.y; acc1[2] += x1.z * w.z; acc1[3] += x1.z * w.w;
        w = Ws4v[(k4 * 4 + 3) * 16 + wcol];
        acc0[0] += x0.w * w.x; acc0[1] += x0.w * w.y; acc0[2] += x0.w * w.z; acc0[3] += x0.w * w.w;
        acc1[0] += x1.w * w.x; acc1[1] += x1.w * w.y; acc1[2] += x1.w * w.z; acc1[3] += x1.w * w.w;
    }

    float f1a = 0.f, f2a = 0.f, f1b = 0.f, f2b = 0.f;
#pragma unroll
    for (int j = 0; j < 4; j++) {
        f1a += acc0[j] * as[cg + j];  f2a += acc0[j] * as[64 + cg + j];
        f1b += acc1[j] * as[cg + j];  f2b += acc1[j] * as[64 + cg + j];
    }
#pragma unroll
    for (int o = 8; o > 0; o >>= 1) {
        f1a += __shfl_xor_sync(0xFFFFFFFF, f1a, o);
        f2a += __shfl_xor_sync(0xFFFFFFFF, f2a, o);
        f1b += __shfl_xor_sync(0xFFFFFFFF, f1b, o);
        f2b += __shfl_xor_sync(0xFFFFFFFF, f2b, o);
    }
    int rowA = r0 + r, rowB = r0 + r + 16;
    if ((tid & 15) == 0) {
        g_rowf[rowA] = make_float2(expf(f1a), expf(0.2f * f1a));
        g_colf[rowA] = make_float2(expf(f2a), expf(0.2f * f2a));
        g_rowf[rowB] = make_float2(expf(f1b), expf(0.2f * f1b));
        g_colf[rowB] = make_float2(expf(f2b), expf(0.2f * f2b));
    }

    // scatter B fragments (global-s layout): h[row][n] -> g_Bf[((s*8+f)*32+l)*2+half]
#pragma unroll
    for (int pass = 0; pass < 2; pass++) {
        int row = pass ? rowB : rowA;
        const float* av = pass ? acc1 : acc0;
        int s = row >> 3;
        int l_lo = row & 3;
        int half = (row >> 2) & 1;
#pragma unroll
        for (int j = 0; j < 4; j++) {
            int n = cg + j;
            int f = n >> 3;
            int l = ((n & 7) << 2) | l_lo;
            g_Bf[(((size_t)(s * 8 + f) * 32 + l) << 1) + half] = f2tf32(av[j]);
        }
    }
}

// ---------------- main kernel ----------------
// grid 256 x 128 threads: rb = blockIdx & 63 (row block of 128), split = blockIdx >> 6.
// 4 warps x 32 rows. Register-software-pipelined s-loop; P-gen uses the
// leaky-max identity: exp(leaky(f1+f2)) = max(e^f1 e^f2, e^.2f1 e^.2f2).
__global__ void __launch_bounds__(128, 2) k_main(const int* __restrict__ adj) {
    extern __shared__ char sm[];
    uint32_t sb = smem_u32(sm);

    int tid = threadIdx.x;
    int wid = tid >> 5;     // 0..3
    int lane = tid & 31;
    int g = lane >> 2;
    int c = lane & 3;

    int rb = blockIdx.x & 63;
    int split = blockIdx.x >> 6;
    int row0 = rb * M_CTA;
    int K0base = split * KSPLIT;

    float e1r[4], e1br[4];
#pragma unroll
    for (int q = 0; q < 4; q++) {
        float2 rf = g_rowf[row0 + wid * 32 + g + q * 8];
        e1r[q] = rf.x; e1br[q] = rf.y;
    }

    float acc[2][8][4];
#pragma unroll
    for (int i = 0; i < 2; i++)
#pragma unroll
        for (int f = 0; f < 8; f++)
#pragma unroll
            for (int q = 0; q < 4; q++) acc[i][f][q] = 0.f;

    float den[4] = {0.f, 0.f, 0.f, 0.f};

    const uint32_t adjOff[2] = {OFF_ADJ0, OFF_ADJ1};
    const uint32_t bfOff[2] = {OFF_BF0, OFF_BF1};
    const uint32_t cfOff[2] = {OFF_CF0, OFF_CF1};

    auto prefetch = [&](int chunk, int buf) {
        int K0 = K0base + chunk * KCHUNK;
        int jr = tid & 15;
        int rbase = tid >> 4;       // 0..7
        const char* srcbase = (const char*)(adj + (size_t)row0 * NN + K0) + jr * 16;
        uint32_t dstbase = sb + adjOff[buf] + jr * 16;
#pragma unroll
        for (int pass = 0; pass < 16; pass++) {
            int row = pass * 8 + rbase;
            CP16(dstbase + row * ADJ_STRIDE, srcbase + (size_t)row * (NN * 4));
        }
        const char* bsrc = (const char*)g_Bf + (size_t)K0 * 256;
        uint32_t bdst = sb + bfOff[buf];
#pragma unroll
        for (int p = 0; p < 8; p++) {
            int piece = tid + p * 128;
            CP16(bdst + piece * 16, bsrc + piece * 16);
        }
        if (tid < 32) {
            CP16(sb + cfOff[buf] + tid * 16, (const char*)(g_colf + K0 + tid * 2));
        }
    };

    prefetch(0, 0); CP_COMMIT();
    prefetch(1, 1); CP_COMMIT();

    for (int it = 0; it < NCHUNK; ++it) {
        int buf = it & 1;
        CP_WAIT1();
        __syncthreads();

        const char* adjS = sm + adjOff[buf];
        const uint32_t* bS = (const uint32_t*)(sm + bfOff[buf]);
        const float2* cfS = (const float2*)(sm + cfOff[buf]);

        // ---- register software pipeline: stage s+1 loads ahead of s compute ----
        float2 rc0[2], rc4[2];
        int ra[2][8];
        uint32_t rbf[2][16];

        // prologue: stage s = 0
        rc0[0] = cfS[c];
        rc4[0] = cfS[c + 4];
#pragma unroll
        for (int q = 0; q < 4; q++) {
            int row = wid * 32 + g + q * 8;
            const int* ar = (const int*)(adjS + row * ADJ_STRIDE) + c;
            ra[0][2 * q] = ar[0];
            ra[0][2 * q + 1] = ar[4];
        }
#pragma unroll
        for (int f = 0; f < 8; f++) {
            uint32_t boff = (f * 32 + lane) * 2;
            rbf[0][2 * f] = bS[boff];
            rbf[0][2 * f + 1] = bS[boff + 1];
        }

#pragma unroll
        for (int s = 0; s < 8; s++) {
            int cur = s & 1, nxt = cur ^ 1;
            if (s < 7) {
                rc0[nxt] = cfS[(s + 1) * 8 + c];
                rc4[nxt] = cfS[(s + 1) * 8 + c + 4];
#pragma unroll
                for (int q = 0; q < 4; q++) {
                    int row = wid * 32 + g + q * 8;
                    const int* ar = (const int*)(adjS + row * ADJ_STRIDE) + (s + 1) * 8 + c;
                    ra[nxt][2 * q] = ar[0];
                    ra[nxt][2 * q + 1] = ar[4];
                }
#pragma unroll
                for (int f = 0; f < 8; f++) {
                    uint32_t boff = (((s + 1) * 8 + f) * 32 + lane) * 2;
                    rbf[nxt][2 * f] = bS[boff];
                    rbf[nxt][2 * f + 1] = bS[boff + 1];
                }
            }

            float2 c0 = rc0[cur], c4 = rc4[cur];
            uint32_t afrag[2][4];
#pragma unroll
            for (int q = 0; q < 4; q++) {
                int ad0 = ra[cur][2 * q];
                int ad4 = ra[cur][2 * q + 1];
                float p0 = fmaxf(e1r[q] * c0.x, e1br[q] * c0.y);
                float p4 = fmaxf(e1r[q] * c4.x, e1br[q] * c4.y);
                p0 = (ad0 != 0) ? p0 : 0.f;
                p4 = (ad4 != 0) ? p4 : 0.f;
                den[q] += p0 + p4;
                afrag[q >> 1][(q & 1) + 0] = f2tf32(p0);
                afrag[q >> 1][(q & 1) + 2] = f2tf32(p4);
            }

#pragma unroll
            for (int f = 0; f < 8; f++) {
                uint32_t b0 = rbf[cur][2 * f];
                uint32_t b1 = rbf[cur][2 * f + 1];
                mma_tf32(acc[0][f][0], acc[0][f][1], acc[0][f][2], acc[0][f][3],
                         afrag[0][0], afrag[0][1], afrag[0][2], afrag[0][3], b0, b1);
                mma_tf32(acc[1][f][0], acc[1][f][1], acc[1][f][2], acc[1][f][3],
                         afrag[1][0], afrag[1][1], afrag[1][2], afrag[1][3], b0, b1);
            }
        }

        __syncthreads();
        if (it + 2 < NCHUNK) prefetch(it + 2, buf);
        CP_COMMIT();
    }

    // ---- epilogue: numerators ----
#pragma unroll
    for (int rf = 0; rf < 2; rf++) {
        int m0 = row0 + wid * 32 + rf * 16 + g;
#pragma unroll
        for (int f = 0; f < 8; f++) {
            int col = f * 8 + c * 2;
            *(float2*)&g_num[split][(size_t)m0 * OUTF + col] =
                make_float2(acc[rf][f][0], acc[rf][f][1]);
            *(float2*)&g_num[split][(size_t)(m0 + 8) * OUTF + col] =
                make_float2(acc[rf][f][2], acc[rf][f][3]);
        }
    }

    // ---- denominators: reduce over the quad (lanes sharing g) ----
#pragma unroll
    for (int q = 0; q < 4; q++) {
        den[q] += __shfl_xor_sync(0xFFFFFFFF, den[q], 1);
        den[q] += __shfl_xor_sync(0xFFFFFFFF, den[q], 2);
    }
    if (c == 0) {
#pragma unroll
        for (int q = 0; q < 4; q++)
            g_den[split][row0 + wid * 32 + g + q * 8] = den[q];
    }
}

// ---------------- combine partials, divide, elu ----------------
__global__ void __launch_bounds__(256) k_comb(float* __restrict__ out) {
    int idx = blockIdx.x * 256 + threadIdx.x;  // over NN*OUTF
    int row = idx >> 6;
    float num = 0.f, den = 0.f;
#pragma unroll
    for (int p = 0; p < NSPLIT; p++) {
        num += g_num[p][idx];
        den += g_den[p][row];
    }
    float v = num / den;
    out[idx] = v > 0.f ? v : expm1f(v);
}

// ---------------- launch ----------------
#define PRE_SMEM (INF_ * OUTF * 4 + 32 * INF_ * 4 + 2 * OUTF * 4)  // 49664

extern "C" void kernel_launch(void* const* d_in, const int* in_sizes, int n_in,
                              void* d_out, int out_size) {
    const float* X = (const float*)d_in[0];
    const int* adj = (const int*)d_in[1];
    const float* W = (const float*)d_in[2];
    const float* a = (const float*)d_in[3];
    float* out = (float*)d_out;

    cudaFuncSetAttribute(k_pre, cudaFuncAttributeMaxDynamicSharedMemorySize, PRE_SMEM);
    cudaFuncSetAttribute(k_main, cudaFuncAttributeMaxDynamicSharedMemorySize, SMEM_BYTES);

    k_pre<<<NN / 32, 256, PRE_SMEM>>>(X, W, a);
    k_main<<<256, 128, SMEM_BYTES>>>(adj);
    k_comb<<<(NN * OUTF) / 256, 256>>>(out);
}